// round 15
// baseline (speedup 1.0000x reference)
#include <cuda_runtime.h>
#include <cuda_fp16.h>
#include <cstdint>

// ---------------------------------------------------------------------------
// Attention_layer, R13: R12 tensor-core path + pair-packed x staging
// (one conflict-free STS.32 per (d, w) instead of two scattered STS.16,
//  F2FP.PACK converts, d-split partial means).
// ---------------------------------------------------------------------------

__device__ __forceinline__ float ex2(float x) {
    float r; asm("ex2.approx.f32 %0,%1;" : "=f"(r) : "f"(x)); return r;
}
__device__ __forceinline__ void mma16816(float& c0, float& c1, float& c2, float& c3,
                                         uint32_t a0, uint32_t a1, uint32_t a2, uint32_t a3,
                                         uint32_t b0, uint32_t b1)
{
    asm volatile("mma.sync.aligned.m16n8k16.row.col.f32.f16.f16.f32 "
                 "{%0,%1,%2,%3}, {%4,%5,%6,%7}, {%8,%9}, {%0,%1,%2,%3};"
                 : "+f"(c0), "+f"(c1), "+f"(c2), "+f"(c3)
                 : "r"(a0), "r"(a1), "r"(a2), "r"(a3), "r"(b0), "r"(b1));
}
__device__ __forceinline__ uint32_t movm(uint32_t x) {
    uint32_t r; asm volatile("movmatrix.sync.aligned.m8n8.trans.b16 %0, %1;"
                             : "=r"(r) : "r"(x));
    return r;
}
__device__ __forceinline__ uint32_t pack_h2(float a, float b) {
    __half2 h = __floats2half2_rn(a, b);
    return *reinterpret_cast<uint32_t*>(&h);
}

// Problem constants
static constexpr int B  = 8;
static constexpr int CH = 64;
static constexpr int D  = 32;
static constexpr int H  = 64;
static constexpr int W  = 64;
static constexpr int S  = 32;
static constexpr int WT = 8;
static constexpr int HW = H * W;

static constexpr int XRW  = 40;         // x row stride (words)
static constexpr int UWX  = 1284;       // per-warp x region words

// smem layout (words)
static constexpr int OFF_U    = 0;                      // 8*1284 = 10272
static constexpr int OFF_WKF  = OFF_U + WT * UWX;       // A-frag order, 1024 w
static constexpr int OFF_WQF  = OFF_WKF + 1024;
static constexpr int OFF_WVF  = OFF_WQF + 1024;
static constexpr int OFF_WOH  = OFF_WVF + 1024;         // fp16 [sp][c] 1024 w
static constexpr int OFF_BF   = OFF_WOH + 1024;         // fp32 bk|bq|bv 96
static constexpr int OFF_BO   = OFF_BF + 96;            // 64
static constexpr int OFF_MX   = OFF_BO + CH;            // x-mean partials [dh][w][c] 1024
static constexpr int OFF_ABH  = OFF_MX + 2 * WT * CH;   // abar fp16: 8*16 w
static constexpr int OFF_OMH  = OFF_ABH + WT * 16;      // om fp16: 8*16 w
static constexpr int OFF_OUT  = OFF_OMH + WT * 16;      // 512
static constexpr int SMEM_FLOATS = OFF_OUT + CH * WT;   // 16320
static constexpr size_t SMEM_BYTES = (size_t)SMEM_FLOATS * 4;  // ~63.8 KB

// Projection GEMM with fragment-order operands.
__device__ __forceinline__ void proj_mma(const uint4* __restrict__ Wf,
                                         const uint32_t* __restrict__ xw,
                                         const float* __restrict__ bf,
                                         int lane, int g, int t,
                                         float C0[2][4], float C1[2][4],
                                         float C2[2][4], float C3[2][4])
{
    float blo[2], bhi[2];
    #pragma unroll
    for (int mt = 0; mt < 2; ++mt) { blo[mt] = bf[16*mt + g]; bhi[mt] = bf[16*mt + 8 + g]; }
    #pragma unroll
    for (int mt = 0; mt < 2; ++mt)
        #pragma unroll
        for (int nt = 0; nt < 4; ++nt) {
            C0[mt][nt] = blo[mt]; C1[mt][nt] = blo[mt];
            C2[mt][nt] = bhi[mt]; C3[mt][nt] = bhi[mt];
        }
    #pragma unroll
    for (int kt = 0; kt < 4; ++kt) {
        uint4 a0 = Wf[(kt * 2 + 0) * 32 + lane];
        uint4 a1 = Wf[(kt * 2 + 1) * 32 + lane];
        #pragma unroll
        for (int nt = 0; nt < 4; ++nt) {
            uint2 bb = *(const uint2*)(xw + (8 * nt + g) * XRW + kt * 8 + 2 * t);
            mma16816(C0[0][nt], C1[0][nt], C2[0][nt], C3[0][nt],
                     a0.x, a0.y, a0.z, a0.w, bb.x, bb.y);
            mma16816(C0[1][nt], C1[1][nt], C2[1][nt], C3[1][nt],
                     a1.x, a1.y, a1.z, a1.w, bb.x, bb.y);
        }
    }
}

__global__ __launch_bounds__(256, 3)
void attn_fused_kernel(const float* __restrict__ x,
                       const float* __restrict__ Wk, const float* __restrict__ bk,
                       const float* __restrict__ Wq, const float* __restrict__ bq,
                       const float* __restrict__ Wv, const float* __restrict__ bv,
                       const float* __restrict__ Wo, const float* __restrict__ bo,
                       const float* __restrict__ factor,
                       float* __restrict__ out)
{
    extern __shared__ float sm[];
    const int tid  = threadIdx.x;
    const int blk  = blockIdx.x;
    const int b    = blk >> 9;
    const int rem  = blk & 511;
    const int h    = rem >> 3;
    const int w0   = (rem & 7) << 3;

    // ---- Stage x: thread = (c-pair, w-pair, d-half).
    //      One half2 (c_even, c_odd) STS.32 per (d, w): conflict-free.
    {
        const int wp2 = (tid & 3) << 1;        // 0,2,4,6
        const int cp  = (tid >> 2) & 31;       // 0..31
        const int dh  = tid >> 7;              // 0..1
        const int c0  = 2 * cp;
        const int d0  = dh * 16;
        const int colp = ((cp >> 3) << 3) | ((cp & 3) << 1) | ((cp >> 2) & 1);
        const float* biA = x + ((size_t)b * CH * D + (size_t)c0 * D + d0) * HW
                             + h * W + w0 + wp2;
        const float* biB = biA + (size_t)D * HW;    // channel c0+1
        __half2* xA = (__half2*)(sm + OFF_U + (size_t)wp2 * UWX);
        __half2* xB = (__half2*)(sm + OFF_U + (size_t)(wp2 + 1) * UWX);
        float s00 = 0.f, s01 = 0.f, s10 = 0.f, s11 = 0.f;
        #pragma unroll 8
        for (int dd = 0; dd < 16; ++dd) {
            int d = d0 + dd;
            float2 va = *(const float2*)(biA + (size_t)dd * HW);
            float2 vb = *(const float2*)(biB + (size_t)dd * HW);
            s00 += va.x; s01 += va.y; s10 += vb.x; s11 += vb.y;
            xA[d * XRW + colp] = __floats2half2_rn(va.x, vb.x);
            xB[d * XRW + colp] = __floats2half2_rn(va.y, vb.y);
        }
        float* mx = sm + OFF_MX + dh * (WT * CH);
        mx[wp2 * CH + c0]           = s00;
        mx[wp2 * CH + c0 + 1]       = s10;
        mx[(wp2 + 1) * CH + c0]     = s01;
        mx[(wp2 + 1) * CH + c0 + 1] = s11;
    }

    // ---- Stage Wk/Wq/Wv in A-fragment order ----
    {
        uint32_t* wkf = (uint32_t*)(sm + OFF_WKF);
        uint32_t* wqf = (uint32_t*)(sm + OFF_WQF);
        uint32_t* wvf = (uint32_t*)(sm + OFF_WVF);
        for (int i = tid; i < 1024; i += 256) {
            int s = i >> 5, wc = i & 31;
            int kt = wc >> 3, tt = wc & 3, r2 = (wc >> 2) & 1;
            int mt = s >> 4, gg = s & 7, r1 = (s >> 3) & 1;
            int addr = ((kt * 2 + mt) * 32 + gg * 4 + tt) * 4 + r1 + 2 * r2;
            float2 vk = *(const float2*)(Wk + s * CH + 2 * wc);
            float2 vq = *(const float2*)(Wq + s * CH + 2 * wc);
            float2 vv = *(const float2*)(Wv + s * CH + 2 * wc);
            wkf[addr] = pack_h2(vk.x, vk.y);
            wqf[addr] = pack_h2(vq.x, vq.y);
            wvf[addr] = pack_h2(vv.x, vv.y);
        }
    }
    // ---- Wo fp16 [sp][c] (s-pair packed) ----
    {
        uint32_t* woh = (uint32_t*)(sm + OFF_WOH);
        for (int i = tid; i < 1024; i += 256) {
            int sp = i >> 6, c2 = i & 63;
            float2 vw = *(const float2*)(Wo + c2 * S + 2 * sp);
            woh[sp * 64 + c2] = pack_h2(vw.x, vw.y);
        }
    }
    if (tid < 96) {
        int m = tid >> 5, tt = tid & 31;
        const float* src = (m == 0) ? bk : ((m == 1) ? bq : bv);
        sm[OFF_BF + tid] = src[tt];
    }
    if (tid < CH) sm[OFF_BO + tid] = bo[tid];
    __syncthreads();

    const int warp = tid >> 5;
    const int lane = tid & 31;
    const int g    = lane >> 2;
    const int t    = lane & 3;

    const uint32_t* xw32 = (const uint32_t*)(sm + OFF_U + warp * UWX);
    const uint4* WkF = (const uint4*)(sm + OFF_WKF);
    const uint4* WqF = (const uint4*)(sm + OFF_WQF);
    const uint4* WvF = (const uint4*)(sm + OFF_WVF);
    const float* bF  = sm + OFF_BF;
    __half* abh  = (__half*)(sm + OFF_ABH) + warp * 32;
    __half* omh  = (__half*)(sm + OFF_OMH) + warp * 32;

    float C0[2][4], C1[2][4], C2[2][4], C3[2][4];

    // ---- V projection (accum packed to fp16 regs for D') ----
    proj_mma(WvF, xw32, bF + 64, lane, g, t, C0, C1, C2, C3);
    __half2 vh[2][2][4];
    #pragma unroll
    for (int mt = 0; mt < 2; ++mt)
        #pragma unroll
        for (int nt = 0; nt < 4; ++nt) {
            uint32_t lo = pack_h2(C0[mt][nt], C1[mt][nt]);
            uint32_t hi = pack_h2(C2[mt][nt], C3[mt][nt]);
            vh[0][mt][nt] = *reinterpret_cast<__half2*>(&lo);
            vh[1][mt][nt] = *reinterpret_cast<__half2*>(&hi);
        }

    // ---- Q projection -> transposed fragments via movmatrix ----
    proj_mma(WqF, xw32, bF + 32, lane, g, t, C0, C1, C2, C3);
    uint32_t QT[4][4];
    #pragma unroll
    for (int mt = 0; mt < 2; ++mt)
        #pragma unroll
        for (int nt = 0; nt < 4; ++nt) {
            QT[2*mt][nt]     = movm(pack_h2(C0[mt][nt], C1[mt][nt]));
            QT[2*mt + 1][nt] = movm(pack_h2(C2[mt][nt], C3[mt][nt]));
        }

    // ---- K projection -> transposed fragments ----
    proj_mma(WkF, xw32, bF, lane, g, t, C0, C1, C2, C3);
    uint32_t KT[4][4];
    #pragma unroll
    for (int mt = 0; mt < 2; ++mt)
        #pragma unroll
        for (int nt = 0; nt < 4; ++nt) {
            KT[2*mt][nt]     = movm(pack_h2(C0[mt][nt], C1[mt][nt]));
            KT[2*mt + 1][nt] = movm(pack_h2(C2[mt][nt], C3[mt][nt]));
        }

    // ---- Scores + softmax + abar, in two j-halves ----
    const float CEXP = 0.17677669529663687f * 1.44269504088896340f;
    float ab0 = 0.f, ab1 = 0.f, ab2 = 0.f, ab3 = 0.f;

    #pragma unroll
    for (int hf = 0; hf < 2; ++hf) {
        float S0[2][2], S1[2][2], S2[2][2], S3[2][2];
        #pragma unroll
        for (int mt = 0; mt < 2; ++mt)
            #pragma unroll
            for (int nl = 0; nl < 2; ++nl) {
                S0[mt][nl] = 0.f; S1[mt][nl] = 0.f; S2[mt][nl] = 0.f; S3[mt][nl] = 0.f;
            }
        #pragma unroll
        for (int kt = 0; kt < 2; ++kt)
            #pragma unroll
            for (int mt = 0; mt < 2; ++mt) {
                uint32_t a0 = KT[2*kt][2*mt],   a1 = KT[2*kt][2*mt + 1];
                uint32_t a2 = KT[2*kt+1][2*mt], a3 = KT[2*kt+1][2*mt + 1];
                #pragma unroll
                for (int nl = 0; nl < 2; ++nl) {
                    int ntj = 2*hf + nl;
                    mma16816(S0[mt][nl], S1[mt][nl], S2[mt][nl], S3[mt][nl],
                             a0, a1, a2, a3, QT[2*kt][ntj], QT[2*kt+1][ntj]);
                }
            }
        #pragma unroll
        for (int nl = 0; nl < 2; ++nl)
            #pragma unroll
            for (int p = 0; p < 2; ++p) {
                float f0 = p ? S1[0][nl] : S0[0][nl];
                float f1 = p ? S3[0][nl] : S2[0][nl];
                float f2 = p ? S1[1][nl] : S0[1][nl];
                float f3 = p ? S3[1][nl] : S2[1][nl];
                float m = fmaxf(fmaxf(f0, f1), fmaxf(f2, f3));
                m = fmaxf(m, __shfl_xor_sync(0xffffffffu, m, 4));
                m = fmaxf(m, __shfl_xor_sync(0xffffffffu, m, 8));
                m = fmaxf(m, __shfl_xor_sync(0xffffffffu, m, 16));
                float e0 = ex2((f0 - m) * CEXP);
                float e1 = ex2((f1 - m) * CEXP);
                float e2 = ex2((f2 - m) * CEXP);
                float e3 = ex2((f3 - m) * CEXP);
                float su = (e0 + e1) + (e2 + e3);
                su += __shfl_xor_sync(0xffffffffu, su, 4);
                su += __shfl_xor_sync(0xffffffffu, su, 8);
                su += __shfl_xor_sync(0xffffffffu, su, 16);
                float r = 1.0f / su;
                ab0 += e0 * r; ab1 += e1 * r; ab2 += e2 * r; ab3 += e3 * r;
            }
    }
    ab0 += __shfl_xor_sync(0xffffffffu, ab0, 1); ab0 += __shfl_xor_sync(0xffffffffu, ab0, 2);
    ab1 += __shfl_xor_sync(0xffffffffu, ab1, 1); ab1 += __shfl_xor_sync(0xffffffffu, ab1, 2);
    ab2 += __shfl_xor_sync(0xffffffffu, ab2, 1); ab2 += __shfl_xor_sync(0xffffffffu, ab2, 2);
    ab3 += __shfl_xor_sync(0xffffffffu, ab3, 1); ab3 += __shfl_xor_sync(0xffffffffu, ab3, 2);
    if (t == 0) {
        abh[g]      = __float2half_rn(ab0 * (1.0f / 32.0f));
        abh[g + 8]  = __float2half_rn(ab1 * (1.0f / 32.0f));
        abh[g + 16] = __float2half_rn(ab2 * (1.0f / 32.0f));
        abh[g + 24] = __float2half_rn(ab3 * (1.0f / 32.0f));
    }
    __syncwarp();

    // ---- D': om[s] = sum_d v[s][d] * abar[d] (HFMA2 on register v) ----
    {
        const uint32_t* abw = (const uint32_t*)abh;
        uint32_t ab2w[4];
        #pragma unroll
        for (int nt = 0; nt < 4; ++nt) ab2w[nt] = abw[4*nt + t];
        __syncwarp();
        #pragma unroll
        for (int mt = 0; mt < 2; ++mt)
            #pragma unroll
            for (int hh = 0; hh < 2; ++hh) {
                __half2 acc = __float2half2_rn(0.f);
                #pragma unroll
                for (int nt = 0; nt < 4; ++nt)
                    acc = __hfma2(vh[hh][mt][nt], *reinterpret_cast<__half2*>(&ab2w[nt]), acc);
                float os = __low2float(acc) + __high2float(acc);
                os += __shfl_xor_sync(0xffffffffu, os, 1);
                os += __shfl_xor_sync(0xffffffffu, os, 2);
                if (t == 0) omh[16*mt + 8*hh + g] = __float2half_rn(os);
            }
    }
    __syncwarp();

    // ---- Phase F: out = mean_d(x) + f*(Wo*om + bo), Wo fp16 ----
    const float fact = factor[0];
    const float mx0 = sm[OFF_MX + warp * CH + lane]
                    + sm[OFF_MX + WT * CH + warp * CH + lane];
    const float mx1 = sm[OFF_MX + warp * CH + lane + 32]
                    + sm[OFF_MX + WT * CH + warp * CH + lane + 32];
    uint4 omq[4];
    #pragma unroll
    for (int u = 0; u < 4; ++u) omq[u] = ((const uint4*)omh)[u];
    const uint32_t* woh = (const uint32_t*)(sm + OFF_WOH);
    __half2 a0h = __float2half2_rn(0.f), a1h = a0h;
    #pragma unroll
    for (int sp = 0; sp < 16; ++sp) {
        uint32_t omw = ((const uint32_t*)&omq[sp >> 2])[sp & 3];
        __half2 om2 = *reinterpret_cast<__half2*>(&omw);
        uint32_t w0w = woh[sp * 64 + lane];
        uint32_t w1w = woh[sp * 64 + lane + 32];
        a0h = __hfma2(*reinterpret_cast<__half2*>(&w0w), om2, a0h);
        a1h = __hfma2(*reinterpret_cast<__half2*>(&w1w), om2, a1h);
    }
    float ac0 = __low2float(a0h) + __high2float(a0h);
    float ac1 = __low2float(a1h) + __high2float(a1h);
    float r0 = mx0 * (1.0f / 32.0f) + fact * (ac0 + sm[OFF_BO + lane]);
    float r1 = mx1 * (1.0f / 32.0f) + fact * (ac1 + sm[OFF_BO + lane + 32]);
    sm[OFF_OUT + lane * 8 + warp]        = r0;
    sm[OFF_OUT + (lane + 32) * 8 + warp] = r1;

    __syncthreads();
    for (int e = tid; e < CH * WT; e += 256) {
        int c = e >> 3, wl = e & 7;
        out[(((size_t)b * CH + c) * H + h) * W + w0 + wl] = sm[OFF_OUT + e];
    }
}

extern "C" void kernel_launch(void* const* d_in, const int* in_sizes, int n_in,
                              void* d_out, int out_size)
{
    (void)in_sizes; (void)n_in; (void)out_size;
    const float* x      = (const float*)d_in[0];
    const float* Wk     = (const float*)d_in[1];
    const float* bk     = (const float*)d_in[2];
    const float* Wq     = (const float*)d_in[3];
    const float* bq     = (const float*)d_in[4];
    const float* Wv     = (const float*)d_in[5];
    const float* bv     = (const float*)d_in[6];
    const float* Wo     = (const float*)d_in[7];
    const float* bo     = (const float*)d_in[8];
    const float* factor = (const float*)d_in[9];
    float* out = (float*)d_out;

    cudaFuncSetAttribute(attn_fused_kernel,
                         cudaFuncAttributeMaxDynamicSharedMemorySize,
                         (int)SMEM_BYTES);
    dim3 grid(B * H * (W / WT));   // 4096
    dim3 block(256);
    attn_fused_kernel<<<grid, block, SMEM_BYTES>>>(
        x, Wk, bk, Wq, bq, Wv, bv, Wo, bo, factor, out);
}

// round 17
// speedup vs baseline: 1.0502x; 1.0502x over previous
#include <cuda_runtime.h>
#include <cuda_fp16.h>
#include <cstdint>

// ---------------------------------------------------------------------------
// Attention_layer, R16 (= R15 + compile fix): fast softmax on tensor-core path.
//  - no max-subtraction (scores are small; softmax is shift-invariant)
//  - ex2.approx.f16x2 exponentials packed over j-parity columns
//  - HADD2-on-shfl reductions, rcp.approx.f32 normalizer, HFMA2 abar accum
// ---------------------------------------------------------------------------

__device__ __forceinline__ void mma16816(float& c0, float& c1, float& c2, float& c3,
                                         uint32_t a0, uint32_t a1, uint32_t a2, uint32_t a3,
                                         uint32_t b0, uint32_t b1)
{
    asm volatile("mma.sync.aligned.m16n8k16.row.col.f32.f16.f16.f32 "
                 "{%0,%1,%2,%3}, {%4,%5,%6,%7}, {%8,%9}, {%0,%1,%2,%3};"
                 : "+f"(c0), "+f"(c1), "+f"(c2), "+f"(c3)
                 : "r"(a0), "r"(a1), "r"(a2), "r"(a3), "r"(b0), "r"(b1));
}
__device__ __forceinline__ uint32_t movm(uint32_t x) {
    uint32_t r; asm volatile("movmatrix.sync.aligned.m8n8.trans.b16 %0, %1;"
                             : "=r"(r) : "r"(x));
    return r;
}
__device__ __forceinline__ uint32_t pack_h2(float a, float b) {
    __half2 h = __floats2half2_rn(a, b);
    return *reinterpret_cast<uint32_t*>(&h);
}
__device__ __forceinline__ __half2 ex2h2(__half2 a) {
    uint32_t x = *reinterpret_cast<uint32_t*>(&a), r;
    asm volatile("ex2.approx.f16x2 %0, %1;" : "=r"(r) : "r"(x));
    return *reinterpret_cast<__half2*>(&r);
}
__device__ __forceinline__ __half2 shfl_hadd2(__half2 v, int m) {
    uint32_t u = *reinterpret_cast<uint32_t*>(&v);
    uint32_t o = __shfl_xor_sync(0xffffffffu, u, m);
    return __hadd2(v, *reinterpret_cast<__half2*>(&o));
}
__device__ __forceinline__ __half2 rcp_h2(__half2 v) {
    float lo = __low2float(v), hi = __high2float(v);
    float rl, rh;
    asm("rcp.approx.f32 %0, %1;" : "=f"(rl) : "f"(lo));
    asm("rcp.approx.f32 %0, %1;" : "=f"(rh) : "f"(hi));
    return __floats2half2_rn(rl, rh);
}

// Problem constants
static constexpr int B  = 8;
static constexpr int CH = 64;
static constexpr int D  = 32;
static constexpr int H  = 64;
static constexpr int W  = 64;
static constexpr int S  = 32;
static constexpr int WT = 8;
static constexpr int HW = H * W;

static constexpr int XRW  = 40;         // x row stride (words)
static constexpr int UWX  = 1284;       // per-warp x region words

// smem layout (words)
static constexpr int OFF_U    = 0;                      // 8*1284 = 10272
static constexpr int OFF_WKF  = OFF_U + WT * UWX;       // A-frag order, 1024 w
static constexpr int OFF_WQF  = OFF_WKF + 1024;
static constexpr int OFF_WVF  = OFF_WQF + 1024;
static constexpr int OFF_WOH  = OFF_WVF + 1024;         // fp16 [sp][c] 1024 w
static constexpr int OFF_BF   = OFF_WOH + 1024;         // fp32 bk|bq|bv 96
static constexpr int OFF_BO   = OFF_BF + 96;            // 64
static constexpr int OFF_MX   = OFF_BO + CH;            // x-mean partials [dh][w][c] 1024
static constexpr int OFF_ABH  = OFF_MX + 2 * WT * CH;   // abar fp16: 8*16 w
static constexpr int OFF_OMH  = OFF_ABH + WT * 16;      // om fp16: 8*16 w
static constexpr int OFF_OUT  = OFF_OMH + WT * 16;      // 512
static constexpr int SMEM_FLOATS = OFF_OUT + CH * WT;   // 16320
static constexpr size_t SMEM_BYTES = (size_t)SMEM_FLOATS * 4;  // ~63.8 KB

// Projection GEMM with fragment-order operands.
__device__ __forceinline__ void proj_mma(const uint4* __restrict__ Wf,
                                         const uint32_t* __restrict__ xw,
                                         const float* __restrict__ bf,
                                         int lane, int g, int t,
                                         float C0[2][4], float C1[2][4],
                                         float C2[2][4], float C3[2][4])
{
    float blo[2], bhi[2];
    #pragma unroll
    for (int mt = 0; mt < 2; ++mt) { blo[mt] = bf[16*mt + g]; bhi[mt] = bf[16*mt + 8 + g]; }
    #pragma unroll
    for (int mt = 0; mt < 2; ++mt)
        #pragma unroll
        for (int nt = 0; nt < 4; ++nt) {
            C0[mt][nt] = blo[mt]; C1[mt][nt] = blo[mt];
            C2[mt][nt] = bhi[mt]; C3[mt][nt] = bhi[mt];
        }
    #pragma unroll
    for (int kt = 0; kt < 4; ++kt) {
        uint4 a0 = Wf[(kt * 2 + 0) * 32 + lane];
        uint4 a1 = Wf[(kt * 2 + 1) * 32 + lane];
        #pragma unroll
        for (int nt = 0; nt < 4; ++nt) {
            uint2 bb = *(const uint2*)(xw + (8 * nt + g) * XRW + kt * 8 + 2 * t);
            mma16816(C0[0][nt], C1[0][nt], C2[0][nt], C3[0][nt],
                     a0.x, a0.y, a0.z, a0.w, bb.x, bb.y);
            mma16816(C0[1][nt], C1[1][nt], C2[1][nt], C3[1][nt],
                     a1.x, a1.y, a1.z, a1.w, bb.x, bb.y);
        }
    }
}

__global__ __launch_bounds__(256, 3)
void attn_fused_kernel(const float* __restrict__ x,
                       const float* __restrict__ Wk, const float* __restrict__ bk,
                       const float* __restrict__ Wq, const float* __restrict__ bq,
                       const float* __restrict__ Wv, const float* __restrict__ bv,
                       const float* __restrict__ Wo, const float* __restrict__ bo,
                       const float* __restrict__ factor,
                       float* __restrict__ out)
{
    extern __shared__ float sm[];
    const int tid  = threadIdx.x;
    const int blk  = blockIdx.x;
    const int b    = blk >> 9;
    const int rem  = blk & 511;
    const int h    = rem >> 3;
    const int w0   = (rem & 7) << 3;

    // ---- Stage x: thread = (c-pair, w-pair, d-half), pair-packed STS.32 ----
    {
        const int wp2 = (tid & 3) << 1;
        const int cp  = (tid >> 2) & 31;
        const int dh  = tid >> 7;
        const int c0  = 2 * cp;
        const int d0  = dh * 16;
        const int colp = ((cp >> 3) << 3) | ((cp & 3) << 1) | ((cp >> 2) & 1);
        const float* biA = x + ((size_t)b * CH * D + (size_t)c0 * D + d0) * HW
                             + h * W + w0 + wp2;
        const float* biB = biA + (size_t)D * HW;
        __half2* xA = (__half2*)(sm + OFF_U + (size_t)wp2 * UWX);
        __half2* xB = (__half2*)(sm + OFF_U + (size_t)(wp2 + 1) * UWX);
        float s00 = 0.f, s01 = 0.f, s10 = 0.f, s11 = 0.f;
        #pragma unroll
        for (int dd = 0; dd < 16; ++dd) {
            int d = d0 + dd;
            float2 va = *(const float2*)(biA + (size_t)dd * HW);
            float2 vb = *(const float2*)(biB + (size_t)dd * HW);
            s00 += va.x; s01 += va.y; s10 += vb.x; s11 += vb.y;
            xA[d * XRW + colp] = __floats2half2_rn(va.x, vb.x);
            xB[d * XRW + colp] = __floats2half2_rn(va.y, vb.y);
        }
        float* mx = sm + OFF_MX + dh * (WT * CH);
        mx[wp2 * CH + c0]           = s00;
        mx[wp2 * CH + c0 + 1]       = s10;
        mx[(wp2 + 1) * CH + c0]     = s01;
        mx[(wp2 + 1) * CH + c0 + 1] = s11;
    }

    // ---- Stage Wk/Wq/Wv in A-fragment order ----
    {
        uint32_t* wkf = (uint32_t*)(sm + OFF_WKF);
        uint32_t* wqf = (uint32_t*)(sm + OFF_WQF);
        uint32_t* wvf = (uint32_t*)(sm + OFF_WVF);
        for (int i = tid; i < 1024; i += 256) {
            int s = i >> 5, wc = i & 31;
            int kt = wc >> 3, tt = wc & 3, r2 = (wc >> 2) & 1;
            int mt = s >> 4, gg = s & 7, r1 = (s >> 3) & 1;
            int addr = ((kt * 2 + mt) * 32 + gg * 4 + tt) * 4 + r1 + 2 * r2;
            float2 vk = *(const float2*)(Wk + s * CH + 2 * wc);
            float2 vq = *(const float2*)(Wq + s * CH + 2 * wc);
            float2 vv = *(const float2*)(Wv + s * CH + 2 * wc);
            wkf[addr] = pack_h2(vk.x, vk.y);
            wqf[addr] = pack_h2(vq.x, vq.y);
            wvf[addr] = pack_h2(vv.x, vv.y);
        }
    }
    // ---- Wo fp16 [sp][c] ----
    {
        uint32_t* woh = (uint32_t*)(sm + OFF_WOH);
        for (int i = tid; i < 1024; i += 256) {
            int sp = i >> 6, c2 = i & 63;
            float2 vw = *(const float2*)(Wo + c2 * S + 2 * sp);
            woh[sp * 64 + c2] = pack_h2(vw.x, vw.y);
        }
    }
    if (tid < 96) {
        int m = tid >> 5, tt = tid & 31;
        const float* src = (m == 0) ? bk : ((m == 1) ? bq : bv);
        sm[OFF_BF + tid] = src[tt];
    }
    if (tid < CH) sm[OFF_BO + tid] = bo[tid];
    __syncthreads();

    const int warp = tid >> 5;
    const int lane = tid & 31;
    const int g    = lane >> 2;
    const int t    = lane & 3;

    const uint32_t* xw32 = (const uint32_t*)(sm + OFF_U + warp * UWX);
    const uint4* WkF = (const uint4*)(sm + OFF_WKF);
    const uint4* WqF = (const uint4*)(sm + OFF_WQF);
    const uint4* WvF = (const uint4*)(sm + OFF_WVF);
    const float* bF  = sm + OFF_BF;
    __half* abh  = (__half*)(sm + OFF_ABH) + warp * 32;
    __half* omh  = (__half*)(sm + OFF_OMH) + warp * 32;

    float C0[2][4], C1[2][4], C2[2][4], C3[2][4];

    // ---- V projection (accum packed to fp16 regs for D') ----
    proj_mma(WvF, xw32, bF + 64, lane, g, t, C0, C1, C2, C3);
    __half2 vh[2][2][4];
    #pragma unroll
    for (int mt = 0; mt < 2; ++mt)
        #pragma unroll
        for (int nt = 0; nt < 4; ++nt) {
            uint32_t lo = pack_h2(C0[mt][nt], C1[mt][nt]);
            uint32_t hi = pack_h2(C2[mt][nt], C3[mt][nt]);
            vh[0][mt][nt] = *reinterpret_cast<__half2*>(&lo);
            vh[1][mt][nt] = *reinterpret_cast<__half2*>(&hi);
        }

    // ---- Q projection -> transposed fragments via movmatrix ----
    proj_mma(WqF, xw32, bF + 32, lane, g, t, C0, C1, C2, C3);
    uint32_t QT[4][4];
    #pragma unroll
    for (int mt = 0; mt < 2; ++mt)
        #pragma unroll
        for (int nt = 0; nt < 4; ++nt) {
            QT[2*mt][nt]     = movm(pack_h2(C0[mt][nt], C1[mt][nt]));
            QT[2*mt + 1][nt] = movm(pack_h2(C2[mt][nt], C3[mt][nt]));
        }

    // ---- K projection -> transposed fragments ----
    proj_mma(WkF, xw32, bF, lane, g, t, C0, C1, C2, C3);
    uint32_t KT[4][4];
    #pragma unroll
    for (int mt = 0; mt < 2; ++mt)
        #pragma unroll
        for (int nt = 0; nt < 4; ++nt) {
            KT[2*mt][nt]     = movm(pack_h2(C0[mt][nt], C1[mt][nt]));
            KT[2*mt + 1][nt] = movm(pack_h2(C2[mt][nt], C3[mt][nt]));
        }

    // ---- Scores + no-max softmax (fp16x2) + abar ----
    const __half2 CEXP2 = __float2half2_rn(0.25506974f);  // log2(e)/sqrt(32)
    __half2 abacc[4];
    #pragma unroll
    for (int u = 0; u < 4; ++u) abacc[u] = __float2half2_rn(0.f);

    #pragma unroll
    for (int hf = 0; hf < 2; ++hf) {
        float S0[2][2], S1[2][2], S2[2][2], S3[2][2];
        #pragma unroll
        for (int mt = 0; mt < 2; ++mt)
            #pragma unroll
            for (int nl = 0; nl < 2; ++nl) {
                S0[mt][nl] = 0.f; S1[mt][nl] = 0.f; S2[mt][nl] = 0.f; S3[mt][nl] = 0.f;
            }
        #pragma unroll
        for (int kt = 0; kt < 2; ++kt)
            #pragma unroll
            for (int mt = 0; mt < 2; ++mt) {
                uint32_t a0 = KT[2*kt][2*mt],   a1 = KT[2*kt][2*mt + 1];
                uint32_t a2 = KT[2*kt+1][2*mt], a3 = KT[2*kt+1][2*mt + 1];
                #pragma unroll
                for (int nl = 0; nl < 2; ++nl) {
                    int ntj = 2*hf + nl;
                    mma16816(S0[mt][nl], S1[mt][nl], S2[mt][nl], S3[mt][nl],
                             a0, a1, a2, a3, QT[2*kt][ntj], QT[2*kt+1][ntj]);
                }
            }
        #pragma unroll
        for (int nl = 0; nl < 2; ++nl) {
            uint32_t p0 = pack_h2(S0[0][nl], S1[0][nl]);
            uint32_t p1 = pack_h2(S2[0][nl], S3[0][nl]);
            uint32_t p2 = pack_h2(S0[1][nl], S1[1][nl]);
            uint32_t p3 = pack_h2(S2[1][nl], S3[1][nl]);
            __half2 e0 = ex2h2(__hmul2(*reinterpret_cast<__half2*>(&p0), CEXP2));
            __half2 e1 = ex2h2(__hmul2(*reinterpret_cast<__half2*>(&p1), CEXP2));
            __half2 e2 = ex2h2(__hmul2(*reinterpret_cast<__half2*>(&p2), CEXP2));
            __half2 e3 = ex2h2(__hmul2(*reinterpret_cast<__half2*>(&p3), CEXP2));
            __half2 su = __hadd2(__hadd2(e0, e1), __hadd2(e2, e3));
            su = shfl_hadd2(su, 4);
            su = shfl_hadd2(su, 8);
            su = shfl_hadd2(su, 16);
            __half2 r = rcp_h2(su);
            abacc[0] = __hfma2(e0, r, abacc[0]);
            abacc[1] = __hfma2(e1, r, abacc[1]);
            abacc[2] = __hfma2(e2, r, abacc[2]);
            abacc[3] = __hfma2(e3, r, abacc[3]);
        }
    }
    #pragma unroll
    for (int u = 0; u < 4; ++u) {
        abacc[u] = shfl_hadd2(abacc[u], 1);
        abacc[u] = shfl_hadd2(abacc[u], 2);
    }
    if (t == 0) {
        #pragma unroll
        for (int u = 0; u < 4; ++u) {
            float a = (__low2float(abacc[u]) + __high2float(abacc[u])) * (1.0f / 32.0f);
            abh[g + 8 * u] = __float2half_rn(a);
        }
    }
    __syncwarp();

    // ---- D': om[s] = sum_d v[s][d] * abar[d] (HFMA2 on register v) ----
    {
        const uint32_t* abw = (const uint32_t*)abh;
        uint32_t ab2w[4];
        #pragma unroll
        for (int nt = 0; nt < 4; ++nt) ab2w[nt] = abw[4*nt + t];
        __syncwarp();
        #pragma unroll
        for (int mt = 0; mt < 2; ++mt)
            #pragma unroll
            for (int hh = 0; hh < 2; ++hh) {
                __half2 acc = __float2half2_rn(0.f);
                #pragma unroll
                for (int nt = 0; nt < 4; ++nt)
                    acc = __hfma2(vh[hh][mt][nt], *reinterpret_cast<__half2*>(&ab2w[nt]), acc);
                float os = __low2float(acc) + __high2float(acc);
                os += __shfl_xor_sync(0xffffffffu, os, 1);
                os += __shfl_xor_sync(0xffffffffu, os, 2);
                if (t == 0) omh[16*mt + 8*hh + g] = __float2half_rn(os);
            }
    }
    __syncwarp();

    // ---- Phase F: out = mean_d(x) + f*(Wo*om + bo), Wo fp16 ----
    const float fact = factor[0];
    const float mx0 = sm[OFF_MX + warp * CH + lane]
                    + sm[OFF_MX + WT * CH + warp * CH + lane];
    const float mx1 = sm[OFF_MX + warp * CH + lane + 32]
                    + sm[OFF_MX + WT * CH + warp * CH + lane + 32];
    uint4 omq[4];
    #pragma unroll
    for (int u = 0; u < 4; ++u) omq[u] = ((const uint4*)omh)[u];
    const uint32_t* woh = (const uint32_t*)(sm + OFF_WOH);
    __half2 a0h = __float2half2_rn(0.f), a1h = a0h;
    #pragma unroll
    for (int sp = 0; sp < 16; ++sp) {
        uint32_t omw = ((const uint32_t*)&omq[sp >> 2])[sp & 3];
        __half2 om2 = *reinterpret_cast<__half2*>(&omw);
        uint32_t w0w = woh[sp * 64 + lane];
        uint32_t w1w = woh[sp * 64 + lane + 32];
        a0h = __hfma2(*reinterpret_cast<__half2*>(&w0w), om2, a0h);
        a1h = __hfma2(*reinterpret_cast<__half2*>(&w1w), om2, a1h);
    }
    float ac0 = __low2float(a0h) + __high2float(a0h);
    float ac1 = __low2float(a1h) + __high2float(a1h);
    float r0 = mx0 * (1.0f / 32.0f) + fact * (ac0 + sm[OFF_BO + lane]);
    float r1 = mx1 * (1.0f / 32.0f) + fact * (ac1 + sm[OFF_BO + lane + 32]);
    sm[OFF_OUT + lane * 8 + warp]        = r0;
    sm[OFF_OUT + (lane + 32) * 8 + warp] = r1;

    __syncthreads();
    for (int e = tid; e < CH * WT; e += 256) {
        int c = e >> 3, wl = e & 7;
        out[(((size_t)b * CH + c) * H + h) * W + w0 + wl] = sm[OFF_OUT + e];
    }
}

extern "C" void kernel_launch(void* const* d_in, const int* in_sizes, int n_in,
                              void* d_out, int out_size)
{
    (void)in_sizes; (void)n_in; (void)out_size;
    const float* x      = (const float*)d_in[0];
    const float* Wk     = (const float*)d_in[1];
    const float* bk     = (const float*)d_in[2];
    const float* Wq     = (const float*)d_in[3];
    const float* bq     = (const float*)d_in[4];
    const float* Wv     = (const float*)d_in[5];
    const float* bv     = (const float*)d_in[6];
    const float* Wo     = (const float*)d_in[7];
    const float* bo     = (const float*)d_in[8];
    const float* factor = (const float*)d_in[9];
    float* out = (float*)d_out;

    cudaFuncSetAttribute(attn_fused_kernel,
                         cudaFuncAttributeMaxDynamicSharedMemorySize,
                         (int)SMEM_BYTES);
    dim3 grid(B * H * (W / WT));   // 4096
    dim3 block(256);
    attn_fused_kernel<<<grid, block, SMEM_BYTES>>>(
        x, Wk, bk, Wq, bq, Wv, bv, Wo, bo, factor, out);
}